// round 2
// baseline (speedup 1.0000x reference)
#include <cuda_runtime.h>
#include <cstdint>

#define NN 50000
#define NE 800000
#define CC 64
#define SCALE_F (2.0f / 3.0f)
#define DIAGW (SCALE_F - 1.0f)

// ---------------- static device scratch (no runtime allocation) ----------------
__device__ float g_dis[2][NN];            // deg then rsqrt(deg) in-place
__device__ int   g_cnt[2][NN];
__device__ int   g_rowptr[2][NN + 1];
__device__ int   g_cursor[2][NN];
__device__ __align__(16) uint2 g_edges[2][NE];          // {src, bits(weight)} per CSR slot
__device__ __align__(16) float g_T[4][(size_t)NN * CC]; // Tx1..Tx4 buffers

// ---------------- init ----------------
__global__ void k_init() {
    int i = blockIdx.x * blockDim.x + threadIdx.x;
    if (i < NN) {
        g_dis[0][i] = 0.f; g_dis[1][i] = 0.f;
        g_cnt[0][i] = 0;   g_cnt[1][i] = 0;
    }
}

// ---------------- degree + histogram ----------------
__global__ void k_degcount(const int* __restrict__ ei,
                           const float* __restrict__ ew) {
    int e = blockIdx.x * blockDim.x + threadIdx.x;
    if (e >= NE) return;
    int a = ei[e];
    int b = ei[NE + e];
    float w = ew[e];
    atomicAdd(&g_dis[0][a], w);
    atomicAdd(&g_dis[1][b], w);
    atomicAdd(&g_cnt[0][a], 1);
    atomicAdd(&g_cnt[1][b], 1);
}

// ---------------- deg -> deg^{-1/2} ----------------
__global__ void k_rsqrt() {
    int i = blockIdx.x * blockDim.x + threadIdx.x;
    if (i < NN) {
        float d0 = g_dis[0][i];
        float d1 = g_dis[1][i];
        g_dis[0][i] = (d0 > 0.f) ? rsqrtf(d0) : 0.f;
        g_dis[1][i] = (d1 > 0.f) ? rsqrtf(d1) : 0.f;
    }
}

// ---------------- exclusive scan of counts -> rowptr, cursor (1 block/dir) ----------------
__global__ void __launch_bounds__(1024) k_scan() {
    int dir = blockIdx.x;
    __shared__ int wsum[32];
    __shared__ int carry;
    int tid = threadIdx.x;
    int lane = tid & 31, wid = tid >> 5;
    if (tid == 0) carry = 0;
    __syncthreads();
    for (int base = 0; base < NN; base += 1024) {
        int i = base + tid;
        int v = (i < NN) ? g_cnt[dir][i] : 0;
        int xv = v;
        #pragma unroll
        for (int o = 1; o < 32; o <<= 1) {
            int t = __shfl_up_sync(0xffffffffu, xv, o);
            if (lane >= o) xv += t;
        }
        if (lane == 31) wsum[wid] = xv;
        __syncthreads();
        if (wid == 0) {
            int s = wsum[lane];
            #pragma unroll
            for (int o = 1; o < 32; o <<= 1) {
                int t = __shfl_up_sync(0xffffffffu, s, o);
                if (lane >= o) s += t;
            }
            wsum[lane] = s;
        }
        __syncthreads();
        int incl = xv + ((wid > 0) ? wsum[wid - 1] : 0);
        int excl = incl - v + carry;
        if (i < NN) { g_rowptr[dir][i] = excl; g_cursor[dir][i] = excl; }
        int total = wsum[31];
        __syncthreads();
        if (tid == 0) carry += total;
        __syncthreads();
    }
    if (tid == 0) g_rowptr[dir][NN] = NE;
}

// ---------------- scatter edges into both CSRs with normalized weights ----------------
__global__ void k_scatter(const int* __restrict__ ei,
                          const float* __restrict__ ew) {
    int e = blockIdx.x * blockDim.x + threadIdx.x;
    if (e >= NE) return;
    int a = ei[e];       // edge_index[0]
    int b = ei[NE + e];  // edge_index[1]
    float w = ew[e];
    float d0a = g_dis[0][a], d0b = g_dis[0][b];
    float d1a = g_dis[1][a], d1b = g_dis[1][b];
    // conv1: row=a, col=b, dis over ei0
    float w0 = -SCALE_F * d0a * w * d0b;
    // conv2: row=b, col=a, dis over ei1
    float w1 = -SCALE_F * d1b * w * d1a;
    int p0 = atomicAdd(&g_cursor[0][a], 1);
    g_edges[0][p0] = make_uint2((unsigned)b, __float_as_uint(w0));
    int p1 = atomicAdd(&g_cursor[1][b], 1);
    g_edges[1][p1] = make_uint2((unsigned)a, __float_as_uint(w1));
}

// ---------------- SpMV:  y = alpha*(diag_w*v + A v) + beta*prev ----------------
// warp per node; lane owns 2 channels (float2)
__global__ void __launch_bounds__(256) k_spmv(int dir, const float* __restrict__ x,
                                              int vsel, int psel, int ysel,
                                              float alpha, float beta) {
    int node = blockIdx.x * 8 + (threadIdx.x >> 5);
    int lane = threadIdx.x & 31;
    if (node >= NN) return;
    const float* __restrict__ v = (vsel < 0) ? x : g_T[vsel];
    float* __restrict__ y = g_T[ysel];
    const uint2* __restrict__ ed = g_edges[dir];
    int s = g_rowptr[dir][node];
    int e = g_rowptr[dir][node + 1];
    int c2 = lane * 2;
    float ax = 0.f, ay = 0.f;
    int j = s;
    for (; j + 4 <= e; j += 4) {
        uint2 e0 = __ldg(&ed[j]);
        uint2 e1 = __ldg(&ed[j + 1]);
        uint2 e2 = __ldg(&ed[j + 2]);
        uint2 e3 = __ldg(&ed[j + 3]);
        float2 v0 = *(const float2*)(v + (size_t)e0.x * CC + c2);
        float2 v1 = *(const float2*)(v + (size_t)e1.x * CC + c2);
        float2 v2 = *(const float2*)(v + (size_t)e2.x * CC + c2);
        float2 v3 = *(const float2*)(v + (size_t)e3.x * CC + c2);
        ax = fmaf(__uint_as_float(e0.y), v0.x, ax);
        ay = fmaf(__uint_as_float(e0.y), v0.y, ay);
        ax = fmaf(__uint_as_float(e1.y), v1.x, ax);
        ay = fmaf(__uint_as_float(e1.y), v1.y, ay);
        ax = fmaf(__uint_as_float(e2.y), v2.x, ax);
        ay = fmaf(__uint_as_float(e2.y), v2.y, ay);
        ax = fmaf(__uint_as_float(e3.y), v3.x, ax);
        ay = fmaf(__uint_as_float(e3.y), v3.y, ay);
    }
    for (; j < e; ++j) {
        uint2 e0 = __ldg(&ed[j]);
        float2 v0 = *(const float2*)(v + (size_t)e0.x * CC + c2);
        ax = fmaf(__uint_as_float(e0.y), v0.x, ax);
        ay = fmaf(__uint_as_float(e0.y), v0.y, ay);
    }
    float2 vm = *(const float2*)(v + (size_t)node * CC + c2);
    float rx = alpha * fmaf(DIAGW, vm.x, ax);
    float ry = alpha * fmaf(DIAGW, vm.y, ay);
    if (beta != 0.f) {
        const float* __restrict__ p = (psel < 0) ? x : g_T[psel];
        float2 pm = *(const float2*)(p + (size_t)node * CC + c2);
        rx = fmaf(beta, pm.x, rx);
        ry = fmaf(beta, pm.y, ry);
    }
    *(float2*)(y + (size_t)node * CC + c2) = make_float2(rx, ry);
}

// ---------------- GEMM: out[:, off:off+64] = sum_k chunk_k @ W[k] + b ----------------
// chunk_0 = x, chunk_k = g_T[k-1].  64-row tiles, 256 threads, micro 2x8 via fma.rn.f32x2
__global__ void __launch_bounds__(256) k_gemm(const float* __restrict__ x,
                                              const float* __restrict__ W,
                                              const float* __restrict__ bias,
                                              float* __restrict__ out, int col_off) {
    __shared__ float Ast[64][64]; // [k][row] (transposed A tile)
    __shared__ float Ws[64][64];  // [k][out]
    int tid = threadIdx.x;
    int tcol = tid & 7;   // 8 groups of 8 output cols
    int trow = tid >> 3;  // 32 groups of 2 rows
    int n0 = blockIdx.x * 64;

    unsigned long long acc[2][4];
    #pragma unroll
    for (int i = 0; i < 2; i++)
        #pragma unroll
        for (int jj = 0; jj < 4; jj++) acc[i][jj] = 0ULL;

    for (int kb = 0; kb < 5; ++kb) {
        const float* __restrict__ Ab = (kb == 0) ? x : g_T[kb - 1];
        const float* __restrict__ Wb = W + kb * 4096;
        __syncthreads();
        // A tile: r varies fastest -> conflict-free smem stores
        #pragma unroll
        for (int it = 0; it < 4; ++it) {
            int idx = tid + it * 256;
            int r  = idx & 63;
            int cq = idx >> 6;   // 0..15
            int row = n0 + r;
            float4 val = make_float4(0.f, 0.f, 0.f, 0.f);
            if (row < NN) val = *(const float4*)(Ab + (size_t)row * 64 + cq * 4);
            Ast[cq * 4 + 0][r] = val.x;
            Ast[cq * 4 + 1][r] = val.y;
            Ast[cq * 4 + 2][r] = val.z;
            Ast[cq * 4 + 3][r] = val.w;
        }
        #pragma unroll
        for (int it = 0; it < 4; ++it) {
            int idx = tid + it * 256;
            ((float4*)Ws)[idx] = ((const float4*)Wb)[idx];
        }
        __syncthreads();
        #pragma unroll 8
        for (int kk = 0; kk < 64; ++kk) {
            float2 a2 = *(const float2*)&Ast[kk][trow * 2];
            ulonglong2 bq0 = *(const ulonglong2*)&Ws[kk][tcol * 8];
            ulonglong2 bq1 = *(const ulonglong2*)&Ws[kk][tcol * 8 + 4];
            unsigned long long B0 = bq0.x, B1 = bq0.y, B2 = bq1.x, B3 = bq1.y;
            unsigned long long A0, A1;
            asm("mov.b64 %0, {%1, %1};" : "=l"(A0) : "f"(a2.x));
            asm("mov.b64 %0, {%1, %1};" : "=l"(A1) : "f"(a2.y));
            asm("fma.rn.f32x2 %0, %1, %2, %0;" : "+l"(acc[0][0]) : "l"(A0), "l"(B0));
            asm("fma.rn.f32x2 %0, %1, %2, %0;" : "+l"(acc[0][1]) : "l"(A0), "l"(B1));
            asm("fma.rn.f32x2 %0, %1, %2, %0;" : "+l"(acc[0][2]) : "l"(A0), "l"(B2));
            asm("fma.rn.f32x2 %0, %1, %2, %0;" : "+l"(acc[0][3]) : "l"(A0), "l"(B3));
            asm("fma.rn.f32x2 %0, %1, %2, %0;" : "+l"(acc[1][0]) : "l"(A1), "l"(B0));
            asm("fma.rn.f32x2 %0, %1, %2, %0;" : "+l"(acc[1][1]) : "l"(A1), "l"(B1));
            asm("fma.rn.f32x2 %0, %1, %2, %0;" : "+l"(acc[1][2]) : "l"(A1), "l"(B2));
            asm("fma.rn.f32x2 %0, %1, %2, %0;" : "+l"(acc[1][3]) : "l"(A1), "l"(B3));
        }
    }
    // epilogue
    float2 bv[4];
    #pragma unroll
    for (int jj = 0; jj < 4; jj++)
        bv[jj] = *(const float2*)(bias + tcol * 8 + jj * 2);
    #pragma unroll
    for (int i = 0; i < 2; i++) {
        int row = n0 + trow * 2 + i;
        if (row < NN) {
            float* o = out + (size_t)row * 128 + col_off + tcol * 8;
            #pragma unroll
            for (int jj = 0; jj < 4; jj++) {
                float2 f;
                asm("mov.b64 {%0, %1}, %2;" : "=f"(f.x), "=f"(f.y) : "l"(acc[i][jj]));
                *(float2*)(o + jj * 2) = make_float2(f.x + bv[jj].x, f.y + bv[jj].y);
            }
        }
    }
}

// ---------------- launch ----------------
extern "C" void kernel_launch(void* const* d_in, const int* in_sizes, int n_in,
                              void* d_out, int out_size) {
    const float* x  = (const float*)d_in[0];
    const int*   ei = (const int*)d_in[1];   // int32: JAX default x64 disabled
    const float* ew = (const float*)d_in[2];
    const float* W1 = (const float*)d_in[3];
    const float* b1 = (const float*)d_in[4];
    const float* W2 = (const float*)d_in[5];
    const float* b2 = (const float*)d_in[6];
    float*       out = (float*)d_out;

    (void)in_sizes; (void)n_in; (void)out_size;

    const int TB = 256;
    // ---- preprocessing: CSR build for both directions ----
    k_init<<<(NN + TB - 1) / TB, TB>>>();
    k_degcount<<<(NE + TB - 1) / TB, TB>>>(ei, ew);
    k_rsqrt<<<(NN + TB - 1) / TB, TB>>>();
    k_scan<<<2, 1024>>>();
    k_scatter<<<(NE + TB - 1) / TB, TB>>>(ei, ew);

    const int SPMV_BLOCKS = (NN + 7) / 8;
    const int GEMM_BLOCKS = (NN + 63) / 64;

    // ---- conv1 (dir 0): Tx1..Tx4 then GEMM into cols [0,64) ----
    k_spmv<<<SPMV_BLOCKS, TB>>>(0, x, -1, -1, 0, 1.0f, 0.0f);   // Tx1 = lhat(x)
    k_spmv<<<SPMV_BLOCKS, TB>>>(0, x,  0, -1, 1, 2.0f, -1.0f);  // Tx2 = 2*lhat(Tx1) - x
    k_spmv<<<SPMV_BLOCKS, TB>>>(0, x,  1,  0, 2, 2.0f, -1.0f);  // Tx3
    k_spmv<<<SPMV_BLOCKS, TB>>>(0, x,  2,  1, 3, 2.0f, -1.0f);  // Tx4
    k_gemm<<<GEMM_BLOCKS, TB>>>(x, W1, b1, out, 0);

    // ---- conv2 (dir 1): same with swapped roles, GEMM into cols [64,128) ----
    k_spmv<<<SPMV_BLOCKS, TB>>>(1, x, -1, -1, 0, 1.0f, 0.0f);
    k_spmv<<<SPMV_BLOCKS, TB>>>(1, x,  0, -1, 1, 2.0f, -1.0f);
    k_spmv<<<SPMV_BLOCKS, TB>>>(1, x,  1,  0, 2, 2.0f, -1.0f);
    k_spmv<<<SPMV_BLOCKS, TB>>>(1, x,  2,  1, 3, 2.0f, -1.0f);
    k_gemm<<<GEMM_BLOCKS, TB>>>(x, W2, b2, out, 64);
}

// round 3
// speedup vs baseline: 1.0907x; 1.0907x over previous
#include <cuda_runtime.h>
#include <cstdint>

#define NN 50000
#define NE 800000
#define CC 64
#define SCALE_F (2.0f / 3.0f)
#define DIAGW (SCALE_F - 1.0f)
#define SCAN_B 1024
#define NBLK ((NN + SCAN_B - 1) / SCAN_B)   // 49

// ---------------- static device scratch (no runtime allocation) ----------------
__device__ float g_dis[2][NN];            // deg then rsqrt(deg) in-place
__device__ int   g_cnt[2][NN];
__device__ int   g_rowptr[2][NN + 1];
__device__ int   g_cursor[2][NN];
__device__ int   g_bsum[2][NBLK];
__device__ int   g_boff[2][NBLK];
__device__ __align__(16) uint2 g_edges[2][NE];              // {src, bits(weight)}
__device__ __align__(16) float g_T[2][4][(size_t)NN * CC];  // per-dir Tx1..Tx4

// ---------------- init ----------------
__global__ void k_init() {
    int i = blockIdx.x * blockDim.x + threadIdx.x;
    if (i < NN) {
        g_dis[0][i] = 0.f; g_dis[1][i] = 0.f;
        g_cnt[0][i] = 0;   g_cnt[1][i] = 0;
    }
}

// ---------------- degree + histogram ----------------
__global__ void k_degcount(const int* __restrict__ ei,
                           const float* __restrict__ ew) {
    int e = blockIdx.x * blockDim.x + threadIdx.x;
    if (e >= NE) return;
    int a = ei[e];
    int b = ei[NE + e];
    float w = ew[e];
    atomicAdd(&g_dis[0][a], w);
    atomicAdd(&g_dis[1][b], w);
    atomicAdd(&g_cnt[0][a], 1);
    atomicAdd(&g_cnt[1][b], 1);
}

// ---------------- deg -> deg^{-1/2} ----------------
__global__ void k_rsqrt() {
    int i = blockIdx.x * blockDim.x + threadIdx.x;
    if (i < NN) {
        float d0 = g_dis[0][i];
        float d1 = g_dis[1][i];
        g_dis[0][i] = (d0 > 0.f) ? rsqrtf(d0) : 0.f;
        g_dis[1][i] = (d1 > 0.f) ? rsqrtf(d1) : 0.f;
    }
}

// ---------------- scan stage 1: per-block exclusive scan, block sums ----------------
__global__ void __launch_bounds__(SCAN_B) k_scan_blk() {
    int dir = blockIdx.y;
    __shared__ int wsum[32];
    int tid = threadIdx.x;
    int lane = tid & 31, wid = tid >> 5;
    int i = blockIdx.x * SCAN_B + tid;
    int v = (i < NN) ? g_cnt[dir][i] : 0;
    int xv = v;
    #pragma unroll
    for (int o = 1; o < 32; o <<= 1) {
        int t = __shfl_up_sync(0xffffffffu, xv, o);
        if (lane >= o) xv += t;
    }
    if (lane == 31) wsum[wid] = xv;
    __syncthreads();
    if (wid == 0) {
        int s = wsum[lane];
        #pragma unroll
        for (int o = 1; o < 32; o <<= 1) {
            int t = __shfl_up_sync(0xffffffffu, s, o);
            if (lane >= o) s += t;
        }
        wsum[lane] = s;
    }
    __syncthreads();
    int incl = xv + ((wid > 0) ? wsum[wid - 1] : 0);
    if (i < NN) g_rowptr[dir][i] = incl - v;   // block-local exclusive
    if (tid == SCAN_B - 1) g_bsum[dir][blockIdx.x] = wsum[31];
}

// ---------------- scan stage 2: scan the NBLK block sums (tiny) ----------------
__global__ void k_scan_top() {
    int dir = blockIdx.x;
    __shared__ int w0tot;
    int tid = threadIdx.x;          // 64 threads
    int lane = tid & 31, w = tid >> 5;
    int v = (tid < NBLK) ? g_bsum[dir][tid] : 0;
    int xv = v;
    #pragma unroll
    for (int o = 1; o < 32; o <<= 1) {
        int t = __shfl_up_sync(0xffffffffu, xv, o);
        if (lane >= o) xv += t;
    }
    if (w == 0 && lane == 31) w0tot = xv;
    __syncthreads();
    int excl = xv - v + ((w == 1) ? w0tot : 0);
    if (tid < NBLK) g_boff[dir][tid] = excl;
}

// ---------------- scan stage 3: add block offsets, init cursors ----------------
__global__ void __launch_bounds__(SCAN_B) k_scan_add() {
    int dir = blockIdx.y;
    int i = blockIdx.x * SCAN_B + threadIdx.x;
    if (i < NN) {
        int r = g_rowptr[dir][i] + g_boff[dir][blockIdx.x];
        g_rowptr[dir][i] = r;
        g_cursor[dir][i] = r;
    }
    if (blockIdx.x == 0 && threadIdx.x == 0) g_rowptr[dir][NN] = NE;
}

// ---------------- scatter edges into both CSRs with normalized weights ----------------
__global__ void k_scatter(const int* __restrict__ ei,
                          const float* __restrict__ ew) {
    int e = blockIdx.x * blockDim.x + threadIdx.x;
    if (e >= NE) return;
    int a = ei[e];       // edge_index[0]
    int b = ei[NE + e];  // edge_index[1]
    float w = ew[e];
    float d0a = g_dis[0][a], d0b = g_dis[0][b];
    float d1a = g_dis[1][a], d1b = g_dis[1][b];
    float w0 = -SCALE_F * d0a * w * d0b;   // conv1: row=a, col=b
    float w1 = -SCALE_F * d1b * w * d1a;   // conv2: row=b, col=a
    int p0 = atomicAdd(&g_cursor[0][a], 1);
    g_edges[0][p0] = make_uint2((unsigned)b, __float_as_uint(w0));
    int p1 = atomicAdd(&g_cursor[1][b], 1);
    g_edges[1][p1] = make_uint2((unsigned)a, __float_as_uint(w1));
}

// ---------------- SpMV:  y = alpha*(diag_w*v + A v) + beta*prev ----------------
// grid.y = dir.  warp per node; lane owns 2 channels (float2). 8-wide MLP loop.
__global__ void __launch_bounds__(256) k_spmv(const float* __restrict__ x,
                                              int vsel, int psel, int ysel,
                                              float alpha, float beta) {
    int dir = blockIdx.y;
    int node = blockIdx.x * 8 + (threadIdx.x >> 5);
    int lane = threadIdx.x & 31;
    if (node >= NN) return;
    const float* __restrict__ v = (vsel < 0) ? x : g_T[dir][vsel];
    float* __restrict__ y = g_T[dir][ysel];
    const uint2* __restrict__ ed = g_edges[dir];
    int s = g_rowptr[dir][node];
    int e = g_rowptr[dir][node + 1];
    int c2 = lane * 2;
    float ax = 0.f, ay = 0.f;
    int j = s;
    for (; j + 8 <= e; j += 8) {
        uint2 ee[8];
        #pragma unroll
        for (int q = 0; q < 8; ++q) ee[q] = __ldg(&ed[j + q]);
        float2 vv[8];
        #pragma unroll
        for (int q = 0; q < 8; ++q)
            vv[q] = *(const float2*)(v + (size_t)ee[q].x * CC + c2);
        #pragma unroll
        for (int q = 0; q < 8; ++q) {
            float w = __uint_as_float(ee[q].y);
            ax = fmaf(w, vv[q].x, ax);
            ay = fmaf(w, vv[q].y, ay);
        }
    }
    for (; j + 4 <= e; j += 4) {
        uint2 ee[4];
        #pragma unroll
        for (int q = 0; q < 4; ++q) ee[q] = __ldg(&ed[j + q]);
        float2 vv[4];
        #pragma unroll
        for (int q = 0; q < 4; ++q)
            vv[q] = *(const float2*)(v + (size_t)ee[q].x * CC + c2);
        #pragma unroll
        for (int q = 0; q < 4; ++q) {
            float w = __uint_as_float(ee[q].y);
            ax = fmaf(w, vv[q].x, ax);
            ay = fmaf(w, vv[q].y, ay);
        }
    }
    for (; j < e; ++j) {
        uint2 e0 = __ldg(&ed[j]);
        float2 v0 = *(const float2*)(v + (size_t)e0.x * CC + c2);
        float w = __uint_as_float(e0.y);
        ax = fmaf(w, v0.x, ax);
        ay = fmaf(w, v0.y, ay);
    }
    float2 vm = *(const float2*)(v + (size_t)node * CC + c2);
    float rx = alpha * fmaf(DIAGW, vm.x, ax);
    float ry = alpha * fmaf(DIAGW, vm.y, ay);
    if (beta != 0.f) {
        const float* __restrict__ p = (psel < 0) ? x : g_T[dir][psel];
        float2 pm = *(const float2*)(p + (size_t)node * CC + c2);
        rx = fmaf(beta, pm.x, rx);
        ry = fmaf(beta, pm.y, ry);
    }
    *(float2*)(y + (size_t)node * CC + c2) = make_float2(rx, ry);
}

// ---------------- GEMM (grid.y = dir): out[:, dir*64:+64] = sum_k chunk_k @ W[k] + b --
__global__ void __launch_bounds__(256) k_gemm(const float* __restrict__ x,
                                              const float* __restrict__ W1,
                                              const float* __restrict__ b1,
                                              const float* __restrict__ W2,
                                              const float* __restrict__ b2,
                                              float* __restrict__ out) {
    __shared__ float Ast[64][64]; // [k][row]
    __shared__ float Ws[64][64];  // [k][out]
    int dir = blockIdx.y;
    const float* __restrict__ W = dir ? W2 : W1;
    const float* __restrict__ bias = dir ? b2 : b1;
    int col_off = dir * 64;
    int tid = threadIdx.x;
    int tcol = tid & 7;
    int trow = tid >> 3;
    int n0 = blockIdx.x * 64;

    unsigned long long acc[2][4];
    #pragma unroll
    for (int i = 0; i < 2; i++)
        #pragma unroll
        for (int jj = 0; jj < 4; jj++) acc[i][jj] = 0ULL;

    for (int kb = 0; kb < 5; ++kb) {
        const float* __restrict__ Ab = (kb == 0) ? x : g_T[dir][kb - 1];
        const float* __restrict__ Wb = W + kb * 4096;
        __syncthreads();
        #pragma unroll
        for (int it = 0; it < 4; ++it) {
            int idx = tid + it * 256;
            int r  = idx & 63;
            int cq = idx >> 6;
            int row = n0 + r;
            float4 val = make_float4(0.f, 0.f, 0.f, 0.f);
            if (row < NN) val = *(const float4*)(Ab + (size_t)row * 64 + cq * 4);
            Ast[cq * 4 + 0][r] = val.x;
            Ast[cq * 4 + 1][r] = val.y;
            Ast[cq * 4 + 2][r] = val.z;
            Ast[cq * 4 + 3][r] = val.w;
        }
        #pragma unroll
        for (int it = 0; it < 4; ++it) {
            int idx = tid + it * 256;
            ((float4*)Ws)[idx] = ((const float4*)Wb)[idx];
        }
        __syncthreads();
        #pragma unroll 8
        for (int kk = 0; kk < 64; ++kk) {
            float2 a2 = *(const float2*)&Ast[kk][trow * 2];
            ulonglong2 bq0 = *(const ulonglong2*)&Ws[kk][tcol * 8];
            ulonglong2 bq1 = *(const ulonglong2*)&Ws[kk][tcol * 8 + 4];
            unsigned long long B0 = bq0.x, B1 = bq0.y, B2 = bq1.x, B3 = bq1.y;
            unsigned long long A0, A1;
            asm("mov.b64 %0, {%1, %1};" : "=l"(A0) : "f"(a2.x));
            asm("mov.b64 %0, {%1, %1};" : "=l"(A1) : "f"(a2.y));
            asm("fma.rn.f32x2 %0, %1, %2, %0;" : "+l"(acc[0][0]) : "l"(A0), "l"(B0));
            asm("fma.rn.f32x2 %0, %1, %2, %0;" : "+l"(acc[0][1]) : "l"(A0), "l"(B1));
            asm("fma.rn.f32x2 %0, %1, %2, %0;" : "+l"(acc[0][2]) : "l"(A0), "l"(B2));
            asm("fma.rn.f32x2 %0, %1, %2, %0;" : "+l"(acc[0][3]) : "l"(A0), "l"(B3));
            asm("fma.rn.f32x2 %0, %1, %2, %0;" : "+l"(acc[1][0]) : "l"(A1), "l"(B0));
            asm("fma.rn.f32x2 %0, %1, %2, %0;" : "+l"(acc[1][1]) : "l"(A1), "l"(B1));
            asm("fma.rn.f32x2 %0, %1, %2, %0;" : "+l"(acc[1][2]) : "l"(A1), "l"(B2));
            asm("fma.rn.f32x2 %0, %1, %2, %0;" : "+l"(acc[1][3]) : "l"(A1), "l"(B3));
        }
    }
    float2 bv[4];
    #pragma unroll
    for (int jj = 0; jj < 4; jj++)
        bv[jj] = *(const float2*)(bias + tcol * 8 + jj * 2);
    #pragma unroll
    for (int i = 0; i < 2; i++) {
        int row = n0 + trow * 2 + i;
        if (row < NN) {
            float* o = out + (size_t)row * 128 + col_off + tcol * 8;
            #pragma unroll
            for (int jj = 0; jj < 4; jj++) {
                float2 f;
                asm("mov.b64 {%0, %1}, %2;" : "=f"(f.x), "=f"(f.y) : "l"(acc[i][jj]));
                *(float2*)(o + jj * 2) = make_float2(f.x + bv[jj].x, f.y + bv[jj].y);
            }
        }
    }
}

// ---------------- launch ----------------
extern "C" void kernel_launch(void* const* d_in, const int* in_sizes, int n_in,
                              void* d_out, int out_size) {
    const float* x  = (const float*)d_in[0];
    const int*   ei = (const int*)d_in[1];
    const float* ew = (const float*)d_in[2];
    const float* W1 = (const float*)d_in[3];
    const float* b1 = (const float*)d_in[4];
    const float* W2 = (const float*)d_in[5];
    const float* b2 = (const float*)d_in[6];
    float*       out = (float*)d_out;

    (void)in_sizes; (void)n_in; (void)out_size;

    const int TB = 256;
    // ---- CSR build (both directions) ----
    k_init<<<(NN + TB - 1) / TB, TB>>>();
    k_degcount<<<(NE + TB - 1) / TB, TB>>>(ei, ew);
    k_rsqrt<<<(NN + TB - 1) / TB, TB>>>();
    k_scan_blk<<<dim3(NBLK, 2), SCAN_B>>>();
    k_scan_top<<<2, 64>>>();
    k_scan_add<<<dim3(NBLK, 2), SCAN_B>>>();
    k_scatter<<<(NE + TB - 1) / TB, TB>>>(ei, ew);

    const dim3 SPMV_G((NN + 7) / 8, 2);
    const dim3 GEMM_G((NN + 63) / 64, 2);

    // ---- both directions per stage (grid.y = dir) ----
    k_spmv<<<SPMV_G, TB>>>(x, -1, -1, 0, 1.0f, 0.0f);   // Tx1 = lhat(x)
    k_spmv<<<SPMV_G, TB>>>(x,  0, -1, 1, 2.0f, -1.0f);  // Tx2 = 2*lhat(Tx1) - x
    k_spmv<<<SPMV_G, TB>>>(x,  1,  0, 2, 2.0f, -1.0f);  // Tx3
    k_spmv<<<SPMV_G, TB>>>(x,  2,  1, 3, 2.0f, -1.0f);  // Tx4
    k_gemm<<<GEMM_G, TB>>>(x, W1, b1, W2, b2, out);
}

// round 4
// speedup vs baseline: 1.2007x; 1.1008x over previous
#include <cuda_runtime.h>
#include <cuda_fp16.h>
#include <cstdint>

#define NN 50000
#define NE 800000
#define CC 64
#define SCALE_F (2.0f / 3.0f)
#define DIAGW (SCALE_F - 1.0f)
#define SCAN_B 1024
#define NBLK ((NN + SCAN_B - 1) / SCAN_B)   // 49

// ---------------- static device scratch ----------------
__device__ float g_dis[2][NN];
__device__ int   g_cnt[2][NN];
__device__ int   g_rowptr[2][NN + 1];
__device__ int   g_cursor[2][NN];
__device__ int   g_bsum[2][NBLK];
__device__ __align__(16) uint2  g_edges[2][NE];              // {src, bits(weight)}
__device__ __align__(16) float  g_T[2][4][(size_t)NN * CC];  // fp32 Tx1..Tx4
__device__ __align__(16) __half g_Th[2][3][(size_t)NN * CC]; // fp16 shadow Tx1..Tx3
__device__ __align__(16) __half g_xh[(size_t)NN * CC];       // fp16 shadow of x

// ---------------- init: zero counters + build fp16 shadow of x ----------------
__global__ void k_init(const float* __restrict__ x) {
    int gtid = blockIdx.x * blockDim.x + threadIdx.x;   // 1.6M threads
    if (gtid < NN) {
        g_dis[0][gtid] = 0.f; g_dis[1][gtid] = 0.f;
        g_cnt[0][gtid] = 0;   g_cnt[1][gtid] = 0;
    }
    if (gtid < NN * (CC / 2)) {
        float2 f = ((const float2*)x)[gtid];
        ((__half2*)g_xh)[gtid] = __float22half2_rn(f);
    }
}

// ---------------- degree + histogram ----------------
__global__ void k_degcount(const int* __restrict__ ei,
                           const float* __restrict__ ew) {
    int e = blockIdx.x * blockDim.x + threadIdx.x;
    if (e >= NE) return;
    int a = ei[e];
    int b = ei[NE + e];
    float w = ew[e];
    atomicAdd(&g_dis[0][a], w);
    atomicAdd(&g_dis[1][b], w);
    atomicAdd(&g_cnt[0][a], 1);
    atomicAdd(&g_cnt[1][b], 1);
}

// ---------------- per-block exclusive scan + block sums + fused rsqrt ----------------
__global__ void __launch_bounds__(SCAN_B) k_scanblk_rsqrt() {
    int dir = blockIdx.y;
    __shared__ int wsum[32];
    int tid = threadIdx.x;
    int lane = tid & 31, wid = tid >> 5;
    int i = blockIdx.x * SCAN_B + tid;
    // fused: deg -> deg^{-1/2}
    if (i < NN) {
        float d = g_dis[dir][i];
        g_dis[dir][i] = (d > 0.f) ? rsqrtf(d) : 0.f;
    }
    int v = (i < NN) ? g_cnt[dir][i] : 0;
    int xv = v;
    #pragma unroll
    for (int o = 1; o < 32; o <<= 1) {
        int t = __shfl_up_sync(0xffffffffu, xv, o);
        if (lane >= o) xv += t;
    }
    if (lane == 31) wsum[wid] = xv;
    __syncthreads();
    if (wid == 0) {
        int s = wsum[lane];
        #pragma unroll
        for (int o = 1; o < 32; o <<= 1) {
            int t = __shfl_up_sync(0xffffffffu, s, o);
            if (lane >= o) s += t;
        }
        wsum[lane] = s;
    }
    __syncthreads();
    int incl = xv + ((wid > 0) ? wsum[wid - 1] : 0);
    if (i < NN) g_rowptr[dir][i] = incl - v;   // block-local exclusive
    if (tid == SCAN_B - 1) g_bsum[dir][blockIdx.x] = wsum[31];
}

// ---------------- add block offsets (top-scan fused: warp0 sums bsum[0..bid)) ----------
__global__ void __launch_bounds__(SCAN_B) k_scan_add() {
    int dir = blockIdx.y;
    __shared__ int boff;
    int tid = threadIdx.x;
    if (tid < 32) {
        int s = 0;
        for (int b = tid; b < (int)blockIdx.x; b += 32) s += g_bsum[dir][b];
        #pragma unroll
        for (int o = 16; o > 0; o >>= 1) s += __shfl_down_sync(0xffffffffu, s, o);
        if (tid == 0) boff = s;
    }
    __syncthreads();
    int i = blockIdx.x * SCAN_B + tid;
    if (i < NN) {
        int r = g_rowptr[dir][i] + boff;
        g_rowptr[dir][i] = r;
        g_cursor[dir][i] = r;
    }
    if (blockIdx.x == 0 && tid == 0) g_rowptr[dir][NN] = NE;
}

// ---------------- scatter edges into both CSRs with normalized weights ----------------
__global__ void k_scatter(const int* __restrict__ ei,
                          const float* __restrict__ ew) {
    int e = blockIdx.x * blockDim.x + threadIdx.x;
    if (e >= NE) return;
    int a = ei[e];
    int b = ei[NE + e];
    float w = ew[e];
    float d0a = g_dis[0][a], d0b = g_dis[0][b];
    float d1a = g_dis[1][a], d1b = g_dis[1][b];
    float w0 = -SCALE_F * d0a * w * d0b;   // conv1: row=a, col=b
    float w1 = -SCALE_F * d1b * w * d1a;   // conv2: row=b, col=a
    int p0 = atomicAdd(&g_cursor[0][a], 1);
    g_edges[0][p0] = make_uint2((unsigned)b, __float_as_uint(w0));
    int p1 = atomicAdd(&g_cursor[1][b], 1);
    g_edges[1][p1] = make_uint2((unsigned)a, __float_as_uint(w1));
}

// ---------------- SpMV:  y = alpha*(diag_w*v + A vh) + beta*prev ----------------
// 16 lanes per node, 4 channels per lane. Gathers read the fp16 shadow; the
// diag and prev terms read fp32. Writes fp32 y and (optionally) fp16 shadow.
__global__ void __launch_bounds__(256) k_spmv(const float* __restrict__ x,
                                              int vsel, int psel, int ysel,
                                              float alpha, float beta, int writeH) {
    int dir = blockIdx.y;
    int node = blockIdx.x * 16 + (threadIdx.x >> 4);
    int lane16 = threadIdx.x & 15;
    if (node >= NN) return;
    const float*  __restrict__ v  = (vsel < 0) ? x : g_T[dir][vsel];
    const __half* __restrict__ vh = (vsel < 0) ? g_xh : g_Th[dir][vsel];
    float* __restrict__ y = g_T[dir][ysel];
    const uint2* __restrict__ ed = g_edges[dir];
    int s = g_rowptr[dir][node];
    int e = g_rowptr[dir][node + 1];
    int c4 = lane16 * 4;                     // 4 channels per lane
    float a0 = 0.f, a1 = 0.f, a2 = 0.f, a3 = 0.f;
    int j = s;
    for (; j + 8 <= e; j += 8) {
        uint2 ee[8];
        #pragma unroll
        for (int q = 0; q < 8; ++q) ee[q] = __ldg(&ed[j + q]);
        uint2 gh[8];
        #pragma unroll
        for (int q = 0; q < 8; ++q)
            gh[q] = *(const uint2*)(vh + (size_t)ee[q].x * CC + c4);
        #pragma unroll
        for (int q = 0; q < 8; ++q) {
            float w = __uint_as_float(ee[q].y);
            float2 f0 = __half22float2(*(const __half2*)&gh[q].x);
            float2 f1 = __half22float2(*(const __half2*)&gh[q].y);
            a0 = fmaf(w, f0.x, a0);
            a1 = fmaf(w, f0.y, a1);
            a2 = fmaf(w, f1.x, a2);
            a3 = fmaf(w, f1.y, a3);
        }
    }
    for (; j < e; ++j) {
        uint2 e0 = __ldg(&ed[j]);
        uint2 g0 = *(const uint2*)(vh + (size_t)e0.x * CC + c4);
        float w = __uint_as_float(e0.y);
        float2 f0 = __half22float2(*(const __half2*)&g0.x);
        float2 f1 = __half22float2(*(const __half2*)&g0.y);
        a0 = fmaf(w, f0.x, a0);
        a1 = fmaf(w, f0.y, a1);
        a2 = fmaf(w, f1.x, a2);
        a3 = fmaf(w, f1.y, a3);
    }
    float4 vm = *(const float4*)(v + (size_t)node * CC + c4);
    float r0 = alpha * fmaf(DIAGW, vm.x, a0);
    float r1 = alpha * fmaf(DIAGW, vm.y, a1);
    float r2 = alpha * fmaf(DIAGW, vm.z, a2);
    float r3 = alpha * fmaf(DIAGW, vm.w, a3);
    if (beta != 0.f) {
        const float* __restrict__ p = (psel < 0) ? x : g_T[dir][psel];
        float4 pm = *(const float4*)(p + (size_t)node * CC + c4);
        r0 = fmaf(beta, pm.x, r0);
        r1 = fmaf(beta, pm.y, r1);
        r2 = fmaf(beta, pm.z, r2);
        r3 = fmaf(beta, pm.w, r3);
    }
    *(float4*)(y + (size_t)node * CC + c4) = make_float4(r0, r1, r2, r3);
    if (writeH) {
        __half* __restrict__ yh = g_Th[dir][ysel];
        __half2 h0 = __floats2half2_rn(r0, r1);
        __half2 h1 = __floats2half2_rn(r2, r3);
        uint2 packed;
        packed.x = *(const unsigned*)&h0;
        packed.y = *(const unsigned*)&h1;
        *(uint2*)(yh + (size_t)node * CC + c4) = packed;
    }
}

// ---------------- GEMM (grid.y = dir): out[:, dir*64:+64] = sum_k chunk_k @ W[k] + b --
__global__ void __launch_bounds__(256) k_gemm(const float* __restrict__ x,
                                              const float* __restrict__ W1,
                                              const float* __restrict__ b1,
                                              const float* __restrict__ W2,
                                              const float* __restrict__ b2,
                                              float* __restrict__ out) {
    __shared__ float Ast[64][64]; // [k][row]
    __shared__ float Ws[64][64];  // [k][out]
    int dir = blockIdx.y;
    const float* __restrict__ W = dir ? W2 : W1;
    const float* __restrict__ bias = dir ? b2 : b1;
    int col_off = dir * 64;
    int tid = threadIdx.x;
    int tcol = tid & 7;
    int trow = tid >> 3;
    int n0 = blockIdx.x * 64;

    unsigned long long acc[2][4];
    #pragma unroll
    for (int i = 0; i < 2; i++)
        #pragma unroll
        for (int jj = 0; jj < 4; jj++) acc[i][jj] = 0ULL;

    for (int kb = 0; kb < 5; ++kb) {
        const float* __restrict__ Ab = (kb == 0) ? x : g_T[dir][kb - 1];
        const float* __restrict__ Wb = W + kb * 4096;
        __syncthreads();
        #pragma unroll
        for (int it = 0; it < 4; ++it) {
            int idx = tid + it * 256;
            int r  = idx & 63;
            int cq = idx >> 6;
            int row = n0 + r;
            float4 val = make_float4(0.f, 0.f, 0.f, 0.f);
            if (row < NN) val = *(const float4*)(Ab + (size_t)row * 64 + cq * 4);
            Ast[cq * 4 + 0][r] = val.x;
            Ast[cq * 4 + 1][r] = val.y;
            Ast[cq * 4 + 2][r] = val.z;
            Ast[cq * 4 + 3][r] = val.w;
        }
        #pragma unroll
        for (int it = 0; it < 4; ++it) {
            int idx = tid + it * 256;
            ((float4*)Ws)[idx] = ((const float4*)Wb)[idx];
        }
        __syncthreads();
        #pragma unroll 8
        for (int kk = 0; kk < 64; ++kk) {
            float2 a2 = *(const float2*)&Ast[kk][trow * 2];
            ulonglong2 bq0 = *(const ulonglong2*)&Ws[kk][tcol * 8];
            ulonglong2 bq1 = *(const ulonglong2*)&Ws[kk][tcol * 8 + 4];
            unsigned long long B0 = bq0.x, B1 = bq0.y, B2 = bq1.x, B3 = bq1.y;
            unsigned long long A0, A1;
            asm("mov.b64 %0, {%1, %1};" : "=l"(A0) : "f"(a2.x));
            asm("mov.b64 %0, {%1, %1};" : "=l"(A1) : "f"(a2.y));
            asm("fma.rn.f32x2 %0, %1, %2, %0;" : "+l"(acc[0][0]) : "l"(A0), "l"(B0));
            asm("fma.rn.f32x2 %0, %1, %2, %0;" : "+l"(acc[0][1]) : "l"(A0), "l"(B1));
            asm("fma.rn.f32x2 %0, %1, %2, %0;" : "+l"(acc[0][2]) : "l"(A0), "l"(B2));
            asm("fma.rn.f32x2 %0, %1, %2, %0;" : "+l"(acc[0][3]) : "l"(A0), "l"(B3));
            asm("fma.rn.f32x2 %0, %1, %2, %0;" : "+l"(acc[1][0]) : "l"(A1), "l"(B0));
            asm("fma.rn.f32x2 %0, %1, %2, %0;" : "+l"(acc[1][1]) : "l"(A1), "l"(B1));
            asm("fma.rn.f32x2 %0, %1, %2, %0;" : "+l"(acc[1][2]) : "l"(A1), "l"(B2));
            asm("fma.rn.f32x2 %0, %1, %2, %0;" : "+l"(acc[1][3]) : "l"(A1), "l"(B3));
        }
    }
    float2 bv[4];
    #pragma unroll
    for (int jj = 0; jj < 4; jj++)
        bv[jj] = *(const float2*)(bias + tcol * 8 + jj * 2);
    #pragma unroll
    for (int i = 0; i < 2; i++) {
        int row = n0 + trow * 2 + i;
        if (row < NN) {
            float* o = out + (size_t)row * 128 + col_off + tcol * 8;
            #pragma unroll
            for (int jj = 0; jj < 4; jj++) {
                float2 f;
                asm("mov.b64 {%0, %1}, %2;" : "=f"(f.x), "=f"(f.y) : "l"(acc[i][jj]));
                *(float2*)(o + jj * 2) = make_float2(f.x + bv[jj].x, f.y + bv[jj].y);
            }
        }
    }
}

// ---------------- launch ----------------
extern "C" void kernel_launch(void* const* d_in, const int* in_sizes, int n_in,
                              void* d_out, int out_size) {
    const float* x  = (const float*)d_in[0];
    const int*   ei = (const int*)d_in[1];
    const float* ew = (const float*)d_in[2];
    const float* W1 = (const float*)d_in[3];
    const float* b1 = (const float*)d_in[4];
    const float* W2 = (const float*)d_in[5];
    const float* b2 = (const float*)d_in[6];
    float*       out = (float*)d_out;

    (void)in_sizes; (void)n_in; (void)out_size;

    const int TB = 256;
    // launches: 0 init, 1 degcount, 2 scanblk+rsqrt, 3 scan_add, 4 scatter,
    //           5..8 spmv (ncu -s 5 profiles the first spmv), 9 gemm
    k_init<<<(NN * (CC / 2) + TB - 1) / TB, TB>>>(x);
    k_degcount<<<(NE + TB - 1) / TB, TB>>>(ei, ew);
    k_scanblk_rsqrt<<<dim3(NBLK, 2), SCAN_B>>>();
    k_scan_add<<<dim3(NBLK, 2), SCAN_B>>>();
    k_scatter<<<(NE + TB - 1) / TB, TB>>>(ei, ew);

    const dim3 SPMV_G((NN + 15) / 16, 2);
    const dim3 GEMM_G((NN + 63) / 64, 2);

    k_spmv<<<SPMV_G, TB>>>(x, -1, -1, 0, 1.0f, 0.0f, 1);   // Tx1 = lhat(x)
    k_spmv<<<SPMV_G, TB>>>(x,  0, -1, 1, 2.0f, -1.0f, 1);  // Tx2 = 2*lhat(Tx1) - x
    k_spmv<<<SPMV_G, TB>>>(x,  1,  0, 2, 2.0f, -1.0f, 1);  // Tx3
    k_spmv<<<SPMV_G, TB>>>(x,  2,  1, 3, 2.0f, -1.0f, 0);  // Tx4 (no fp16 shadow needed)
    k_gemm<<<GEMM_G, TB>>>(x, W1, b1, W2, b2, out);
}

// round 5
// speedup vs baseline: 1.2337x; 1.0275x over previous
#include <cuda_runtime.h>
#include <cuda_fp16.h>
#include <cstdint>

#define NN 50000
#define NE 800000
#define CC 64
#define SCALE_F (2.0f / 3.0f)
#define DIAGW (SCALE_F - 1.0f)
#define SCAN_B 1024
#define NBLK ((NN + SCAN_B - 1) / SCAN_B)   // 49
#define MASK48 0xFFFFFFFFFFFFULL

// ---------------- static device scratch (zero-init at module load; every call
// restores the zero invariant for the tables that need it) ----------------
__device__ unsigned long long g_deg64[2][NN]; // packed {cnt:16, wsum:48 fixed 2^-32}
__device__ unsigned g_agg[2][NBLK];           // lookback aggregates (bit31 = published)
__device__ float g_dis[2][NN];
__device__ int   g_rowptr[2][NN + 1];
__device__ int   g_cursor[2][NN];
__device__ __align__(16) uint2  g_edges[2][NE];              // {src, bits(weight)}
__device__ __align__(16) float  g_T[2][4][(size_t)NN * CC];  // fp32 Tx1..Tx4
__device__ __align__(16) __half g_Th[2][3][(size_t)NN * CC]; // fp16 shadow Tx1..Tx3
__device__ __align__(16) __half g_xh[(size_t)NN * CC];       // fp16 shadow of x

// ---------------- launch 0: packed degree/count atomics + fp16 shadow of x ------------
__global__ void k_degcount_xh(const int* __restrict__ ei,
                              const float* __restrict__ ew,
                              const float* __restrict__ x) {
    int e = blockIdx.x * blockDim.x + threadIdx.x;
    if (e >= NE) return;
    int a = ei[e];
    int b = ei[NE + e];
    float w = ew[e];
    unsigned long long pv = (1ULL << 48) + (unsigned long long)(w * 4294967296.0f);
    atomicAdd(&g_deg64[0][a], pv);
    atomicAdd(&g_deg64[1][b], pv);
    // fp16 shadow of x: 1.6M half2 elements, 2 per thread
    float2 f0 = ((const float2*)x)[e];
    ((__half2*)g_xh)[e] = __float22half2_rn(f0);
    float2 f1 = ((const float2*)x)[e + NE];
    ((__half2*)g_xh)[e + NE] = __float22half2_rn(f1);
}

// ---------------- launch 1: single-pass scan (decoupled lookback) + rsqrt -------------
__global__ void __launch_bounds__(SCAN_B) k_scan_fused() {
    int dir = blockIdx.y;
    __shared__ int wsum[32];
    __shared__ int s_boff;
    int tid = threadIdx.x;
    int lane = tid & 31, wid = tid >> 5;
    int i = blockIdx.x * SCAN_B + tid;
    int v = 0;
    if (i < NN) {
        unsigned long long p = g_deg64[dir][i];
        g_deg64[dir][i] = 0ULL;            // restore zero invariant for next call
        v = (int)(p >> 48);
        float deg = (float)(p & MASK48) * 2.3283064365386963e-10f; // * 2^-32
        g_dis[dir][i] = (deg > 0.f) ? rsqrtf(deg) : 0.f;
    }
    // block-local scan
    int xv = v;
    #pragma unroll
    for (int o = 1; o < 32; o <<= 1) {
        int t = __shfl_up_sync(0xffffffffu, xv, o);
        if (lane >= o) xv += t;
    }
    if (lane == 31) wsum[wid] = xv;
    __syncthreads();
    if (wid == 0) {
        int s = wsum[lane];
        #pragma unroll
        for (int o = 1; o < 32; o <<= 1) {
            int t = __shfl_up_sync(0xffffffffu, s, o);
            if (lane >= o) s += t;
        }
        wsum[lane] = s;
    }
    __syncthreads();
    int incl = xv + ((wid > 0) ? wsum[wid - 1] : 0);
    int total = wsum[31];
    // publish aggregate (single word carries flag+value -> no extra fence needed)
    if (tid == 0) atomicExch(&g_agg[dir][blockIdx.x], 0x80000000u | (unsigned)total);
    // lane-parallel lookback over predecessors
    if (wid == 0) {
        int s = 0;
        for (int o = lane + 1; o <= (int)blockIdx.x; o += 32) {
            unsigned a;
            do { a = *(volatile unsigned*)&g_agg[dir][blockIdx.x - o]; }
            while (!(a & 0x80000000u));
            s += (int)(a & 0x7FFFFFFFu);
        }
        #pragma unroll
        for (int o2 = 16; o2 > 0; o2 >>= 1) s += __shfl_down_sync(0xffffffffu, s, o2);
        if (lane == 0) s_boff = s;
    }
    __syncthreads();
    int boff = s_boff;
    if (i < NN) {
        int r = (incl - v) + boff;
        g_rowptr[dir][i] = r;
        g_cursor[dir][i] = r;
    }
    if (blockIdx.x == 0 && tid == 0) g_rowptr[dir][NN] = NE;
}

// ---------------- launch 2: scatter edges into both CSRs (+ re-zero g_agg) ------------
__global__ void k_scatter(const int* __restrict__ ei,
                          const float* __restrict__ ew) {
    int e = blockIdx.x * blockDim.x + threadIdx.x;
    if (e < 2 * NBLK) ((unsigned*)g_agg)[e] = 0;   // restore zero invariant
    if (e >= NE) return;
    int a = ei[e];
    int b = ei[NE + e];
    float w = ew[e];
    float d0a = g_dis[0][a], d0b = g_dis[0][b];
    float d1a = g_dis[1][a], d1b = g_dis[1][b];
    float w0 = -SCALE_F * d0a * w * d0b;   // conv1: row=a, col=b
    float w1 = -SCALE_F * d1b * w * d1a;   // conv2: row=b, col=a
    int p0 = atomicAdd(&g_cursor[0][a], 1);
    g_edges[0][p0] = make_uint2((unsigned)b, __float_as_uint(w0));
    int p1 = atomicAdd(&g_cursor[1][b], 1);
    g_edges[1][p1] = make_uint2((unsigned)a, __float_as_uint(w1));
}

// ---------------- SpMV:  y = alpha*(diag_w*v + A vh) + beta*prev ----------------
// 16 lanes per node, 4 channels per lane. Gathers read the fp16 shadow.
__global__ void __launch_bounds__(256) k_spmv(const float* __restrict__ x,
                                              int vsel, int psel, int ysel,
                                              float alpha, float beta, int writeH) {
    int dir = blockIdx.y;
    int node = blockIdx.x * 16 + (threadIdx.x >> 4);
    int lane16 = threadIdx.x & 15;
    if (node >= NN) return;
    const float*  __restrict__ v  = (vsel < 0) ? x : g_T[dir][vsel];
    const __half* __restrict__ vh = (vsel < 0) ? g_xh : g_Th[dir][vsel];
    float* __restrict__ y = g_T[dir][ysel];
    const uint2* __restrict__ ed = g_edges[dir];
    int s = g_rowptr[dir][node];
    int e = g_rowptr[dir][node + 1];
    int c4 = lane16 * 4;
    float a0 = 0.f, a1 = 0.f, a2 = 0.f, a3 = 0.f;
    int j = s;
    for (; j + 8 <= e; j += 8) {
        uint2 ee[8];
        #pragma unroll
        for (int q = 0; q < 8; ++q) ee[q] = __ldg(&ed[j + q]);
        uint2 gh[8];
        #pragma unroll
        for (int q = 0; q < 8; ++q)
            gh[q] = *(const uint2*)(vh + (size_t)ee[q].x * CC + c4);
        #pragma unroll
        for (int q = 0; q < 8; ++q) {
            float w = __uint_as_float(ee[q].y);
            float2 f0 = __half22float2(*(const __half2*)&gh[q].x);
            float2 f1 = __half22float2(*(const __half2*)&gh[q].y);
            a0 = fmaf(w, f0.x, a0);
            a1 = fmaf(w, f0.y, a1);
            a2 = fmaf(w, f1.x, a2);
            a3 = fmaf(w, f1.y, a3);
        }
    }
    for (; j < e; ++j) {
        uint2 e0 = __ldg(&ed[j]);
        uint2 g0 = *(const uint2*)(vh + (size_t)e0.x * CC + c4);
        float w = __uint_as_float(e0.y);
        float2 f0 = __half22float2(*(const __half2*)&g0.x);
        float2 f1 = __half22float2(*(const __half2*)&g0.y);
        a0 = fmaf(w, f0.x, a0);
        a1 = fmaf(w, f0.y, a1);
        a2 = fmaf(w, f1.x, a2);
        a3 = fmaf(w, f1.y, a3);
    }
    float4 vm = *(const float4*)(v + (size_t)node * CC + c4);
    float r0 = alpha * fmaf(DIAGW, vm.x, a0);
    float r1 = alpha * fmaf(DIAGW, vm.y, a1);
    float r2 = alpha * fmaf(DIAGW, vm.z, a2);
    float r3 = alpha * fmaf(DIAGW, vm.w, a3);
    if (beta != 0.f) {
        const float* __restrict__ p = (psel < 0) ? x : g_T[dir][psel];
        float4 pm = *(const float4*)(p + (size_t)node * CC + c4);
        r0 = fmaf(beta, pm.x, r0);
        r1 = fmaf(beta, pm.y, r1);
        r2 = fmaf(beta, pm.z, r2);
        r3 = fmaf(beta, pm.w, r3);
    }
    *(float4*)(y + (size_t)node * CC + c4) = make_float4(r0, r1, r2, r3);
    if (writeH) {
        __half* __restrict__ yh = g_Th[dir][ysel];
        __half2 h0 = __floats2half2_rn(r0, r1);
        __half2 h1 = __floats2half2_rn(r2, r3);
        uint2 packed;
        packed.x = *(const unsigned*)&h0;
        packed.y = *(const unsigned*)&h1;
        *(uint2*)(yh + (size_t)node * CC + c4) = packed;
    }
}

// ---------------- GEMM (grid.y = dir): out[:, dir*64:+64] = sum_k chunk_k @ W[k] + b --
__global__ void __launch_bounds__(256) k_gemm(const float* __restrict__ x,
                                              const float* __restrict__ W1,
                                              const float* __restrict__ b1,
                                              const float* __restrict__ W2,
                                              const float* __restrict__ b2,
                                              float* __restrict__ out) {
    __shared__ float Ast[64][64]; // [k][row]
    __shared__ float Ws[64][64];  // [k][out]
    int dir = blockIdx.y;
    const float* __restrict__ W = dir ? W2 : W1;
    const float* __restrict__ bias = dir ? b2 : b1;
    int col_off = dir * 64;
    int tid = threadIdx.x;
    int tcol = tid & 7;
    int trow = tid >> 3;
    int n0 = blockIdx.x * 64;

    unsigned long long acc[2][4];
    #pragma unroll
    for (int i = 0; i < 2; i++)
        #pragma unroll
        for (int jj = 0; jj < 4; jj++) acc[i][jj] = 0ULL;

    for (int kb = 0; kb < 5; ++kb) {
        const float* __restrict__ Ab = (kb == 0) ? x : g_T[dir][kb - 1];
        const float* __restrict__ Wb = W + kb * 4096;
        __syncthreads();
        #pragma unroll
        for (int it = 0; it < 4; ++it) {
            int idx = tid + it * 256;
            int r  = idx & 63;
            int cq = idx >> 6;
            int row = n0 + r;
            float4 val = make_float4(0.f, 0.f, 0.f, 0.f);
            if (row < NN) val = *(const float4*)(Ab + (size_t)row * 64 + cq * 4);
            Ast[cq * 4 + 0][r] = val.x;
            Ast[cq * 4 + 1][r] = val.y;
            Ast[cq * 4 + 2][r] = val.z;
            Ast[cq * 4 + 3][r] = val.w;
        }
        #pragma unroll
        for (int it = 0; it < 4; ++it) {
            int idx = tid + it * 256;
            ((float4*)Ws)[idx] = ((const float4*)Wb)[idx];
        }
        __syncthreads();
        #pragma unroll 8
        for (int kk = 0; kk < 64; ++kk) {
            float2 a2 = *(const float2*)&Ast[kk][trow * 2];
            ulonglong2 bq0 = *(const ulonglong2*)&Ws[kk][tcol * 8];
            ulonglong2 bq1 = *(const ulonglong2*)&Ws[kk][tcol * 8 + 4];
            unsigned long long B0 = bq0.x, B1 = bq0.y, B2 = bq1.x, B3 = bq1.y;
            unsigned long long A0, A1;
            asm("mov.b64 %0, {%1, %1};" : "=l"(A0) : "f"(a2.x));
            asm("mov.b64 %0, {%1, %1};" : "=l"(A1) : "f"(a2.y));
            asm("fma.rn.f32x2 %0, %1, %2, %0;" : "+l"(acc[0][0]) : "l"(A0), "l"(B0));
            asm("fma.rn.f32x2 %0, %1, %2, %0;" : "+l"(acc[0][1]) : "l"(A0), "l"(B1));
            asm("fma.rn.f32x2 %0, %1, %2, %0;" : "+l"(acc[0][2]) : "l"(A0), "l"(B2));
            asm("fma.rn.f32x2 %0, %1, %2, %0;" : "+l"(acc[0][3]) : "l"(A0), "l"(B3));
            asm("fma.rn.f32x2 %0, %1, %2, %0;" : "+l"(acc[1][0]) : "l"(A1), "l"(B0));
            asm("fma.rn.f32x2 %0, %1, %2, %0;" : "+l"(acc[1][1]) : "l"(A1), "l"(B1));
            asm("fma.rn.f32x2 %0, %1, %2, %0;" : "+l"(acc[1][2]) : "l"(A1), "l"(B2));
            asm("fma.rn.f32x2 %0, %1, %2, %0;" : "+l"(acc[1][3]) : "l"(A1), "l"(B3));
        }
    }
    float2 bv[4];
    #pragma unroll
    for (int jj = 0; jj < 4; jj++)
        bv[jj] = *(const float2*)(bias + tcol * 8 + jj * 2);
    #pragma unroll
    for (int i = 0; i < 2; i++) {
        int row = n0 + trow * 2 + i;
        if (row < NN) {
            float* o = out + (size_t)row * 128 + col_off + tcol * 8;
            #pragma unroll
            for (int jj = 0; jj < 4; jj++) {
                float2 f;
                asm("mov.b64 {%0, %1}, %2;" : "=f"(f.x), "=f"(f.y) : "l"(acc[i][jj]));
                *(float2*)(o + jj * 2) = make_float2(f.x + bv[jj].x, f.y + bv[jj].y);
            }
        }
    }
}

// ---------------- launch ----------------
extern "C" void kernel_launch(void* const* d_in, const int* in_sizes, int n_in,
                              void* d_out, int out_size) {
    const float* x  = (const float*)d_in[0];
    const int*   ei = (const int*)d_in[1];
    const float* ew = (const float*)d_in[2];
    const float* W1 = (const float*)d_in[3];
    const float* b1 = (const float*)d_in[4];
    const float* W2 = (const float*)d_in[5];
    const float* b2 = (const float*)d_in[6];
    float*       out = (float*)d_out;

    (void)in_sizes; (void)n_in; (void)out_size;

    const int TB = 256;
    // launches: 0 degcount+xh, 1 scan_fused, 2 scatter, 3..6 spmv, 7 gemm
    // (the ncu slot has been landing on my launch index 3 -> spmv1 next round)
    k_degcount_xh<<<(NE + TB - 1) / TB, TB>>>(ei, ew, x);
    k_scan_fused<<<dim3(NBLK, 2), SCAN_B>>>();
    k_scatter<<<(NE + TB - 1) / TB, TB>>>(ei, ew);

    const dim3 SPMV_G((NN + 15) / 16, 2);
    const dim3 GEMM_G((NN + 63) / 64, 2);

    k_spmv<<<SPMV_G, TB>>>(x, -1, -1, 0, 1.0f, 0.0f, 1);   // Tx1 = lhat(x)
    k_spmv<<<SPMV_G, TB>>>(x,  0, -1, 1, 2.0f, -1.0f, 1);  // Tx2 = 2*lhat(Tx1) - x
    k_spmv<<<SPMV_G, TB>>>(x,  1,  0, 2, 2.0f, -1.0f, 1);  // Tx3
    k_spmv<<<SPMV_G, TB>>>(x,  2,  1, 3, 2.0f, -1.0f, 0);  // Tx4
    k_gemm<<<GEMM_G, TB>>>(x, W1, b1, W2, b2, out);
}